// round 4
// baseline (speedup 1.0000x reference)
#include <cuda_runtime.h>

// BoidPolicy: all-pairs boids on a unit torus, N=8192, out acc [N,2] f32.
//
// Pipeline (graph-capturable, no allocations):
//  kA: cell ids (8x8 grid), stable in-warp ranks, per-group histograms
//  kB: prefix sums -> scatter offsets
//  kC: scatter into sorted packed SoA (float4 = x0,x1,y0,y1 per j-pair) + orig idx
//  kD: toroidal bounding boxes for 128 j-chunks (64 boids) and 256 i-tiles (32)
//  k1: O(N^2) pass with per-(tile,chunk) conservative cull; packed f32x2 math
//  k2: reduce 16 slot-partials per boid + epilogue, scatter to original order

#define NB      8192
#define NCELL   64            // 8x8 cells
#define NGRP    (NB / 32)     // 256 warp-groups for the sort
#define CHUNK   64
#define NCHUNK  (NB / CHUNK)  // 128
#define NTILE   (NB / 32)     // 256 i-tiles
#define NSLOT   16
#define KPER    (NCHUNK / NSLOT)  // 8 chunks per slot

#define SEP2F   4e-4f
#define PERC2F  0.04f
#define EPSF    1e-8f
#define MAGIC   12582912.0f   // 1.5 * 2^23

typedef unsigned long long u64;

__device__ float4 g_pos4[NB / 2];     // sorted, packed (xA,xB,yA,yB)
__device__ float4 g_vel4[NB / 2];
__device__ int    g_orig[NB];
__device__ int    g_cellid[NB];
__device__ int    g_lrank[NB];
__device__ int    g_cnt[NGRP * NCELL];
__device__ int    g_off[NGRP * NCELL];
__device__ float4 g_bboxJ[NCHUNK];    // (cx,cy,hx,hy)
__device__ float4 g_bboxI[NTILE];
__device__ float  g_part[7 * NSLOT * NB];

__device__ __forceinline__ u64 pack2(float lo, float hi) {
    u64 r; asm("mov.b64 %0,{%1,%2};" : "=l"(r) : "f"(lo), "f"(hi)); return r;
}
__device__ __forceinline__ void unpack2(u64 v, float& lo, float& hi) {
    asm("mov.b64 {%0,%1},%2;" : "=f"(lo), "=f"(hi) : "l"(v));
}
__device__ __forceinline__ u64 f2add(u64 a, u64 b) {
    u64 d; asm("add.rn.f32x2 %0,%1,%2;" : "=l"(d) : "l"(a), "l"(b)); return d;
}
__device__ __forceinline__ u64 f2mul(u64 a, u64 b) {
    u64 d; asm("mul.rn.f32x2 %0,%1,%2;" : "=l"(d) : "l"(a), "l"(b)); return d;
}
__device__ __forceinline__ u64 f2fma(u64 a, u64 b, u64 c) {
    u64 d; asm("fma.rn.f32x2 %0,%1,%2,%3;" : "=l"(d) : "l"(a), "l"(b), "l"(c)); return d;
}
// per-half: (t >= 0) ? 1.0f : 0.0f   (exact: copysign(0.5,t)+0.5)
__device__ __forceinline__ u64 f2mask(u64 t, u64 half2) {
    u64 s = (t & 0x8000000080000000ULL) | 0x3F0000003F000000ULL;
    return f2add(s, half2);
}
__device__ __forceinline__ float wrap1(float d) { return d - rintf(d); }

// ---------------- kA: cells + stable local ranks + histograms ----------------
__global__ void kA_cells(const float2* __restrict__ pos)
{
    __shared__ int scnt[8][NCELL];
    const int tid = threadIdx.x;
    for (int t = tid; t < 8 * NCELL; t += 256) ((int*)scnt)[t] = 0;
    __syncthreads();

    const int w    = tid >> 5;
    const int lane = tid & 31;
    const int e    = (blockIdx.x * 8 + w) * 32 + lane;
    const float2 p = pos[e];
    int cx = (int)(p.x * 8.0f); cx = cx < 0 ? 0 : (cx > 7 ? 7 : cx);
    int cy = (int)(p.y * 8.0f); cy = cy < 0 ? 0 : (cy > 7 ? 7 : cy);
    const int cell = cy * 8 + cx;

    const unsigned peers = __match_any_sync(0xffffffffu, cell);
    g_cellid[e] = cell;
    g_lrank[e]  = __popc(peers & ((1u << lane) - 1u));
    if ((__ffs(peers) - 1) == lane)
        scnt[w][cell] = __popc(peers);
    __syncthreads();

    for (int t = tid; t < 8 * NCELL; t += 256)
        g_cnt[blockIdx.x * 8 * NCELL + t] = ((int*)scnt)[t];
}

// ---------------- kB: prefix sums -> scatter offsets ----------------
__global__ void kB_prefix()
{
    const int c = threadIdx.x;   // 64 threads, one per cell
    int run = 0;
    for (int g = 0; g < NGRP; ++g) {
        const int v = g_cnt[g * NCELL + c];
        g_off[g * NCELL + c] = run;
        run += v;
    }
    __shared__ int tot[NCELL];
    tot[c] = run;
    __syncthreads();
    int base = 0;
    for (int c2 = 0; c2 < c; ++c2) base += tot[c2];
    for (int g = 0; g < NGRP; ++g) g_off[g * NCELL + c] += base;
}

// ---------------- kC: scatter into sorted packed SoA ----------------
__global__ void kC_scatter(const float2* __restrict__ pos,
                           const float2* __restrict__ vel)
{
    const int e   = blockIdx.x * 256 + threadIdx.x;
    const int c   = g_cellid[e];
    const int dst = g_off[(e >> 5) * NCELL + c] + g_lrank[e];
    const float2 p = pos[e];
    const float2 v = vel[e];
    float* P = (float*)g_pos4;
    float* V = (float*)g_vel4;
    const int b = (dst >> 1) * 4 + (dst & 1);
    P[b] = p.x;  P[b + 2] = p.y;
    V[b] = v.x;  V[b + 2] = v.y;
    g_orig[dst] = e;
}

// ---------------- kD: toroidal bounding boxes ----------------
__global__ void kD_bbox()
{
    const int b   = blockIdx.x;
    const int tid = threadIdx.x;      // 64 threads
    int base, n;
    if (b < NCHUNK) { base = b * CHUNK; n = CHUNK; }
    else            { base = (b - NCHUNK) * 32; n = 32; }

    const float* P = (const float*)g_pos4;
    const float x0 = P[(base >> 1) * 4 + (base & 1)];
    const float y0 = P[(base >> 1) * 4 + 2 + (base & 1)];

    float rx = 0.0f, ry = 0.0f;       // element 0 has rel 0, neutral for inactive
    if (tid < n) {
        const int idx = base + tid;
        const float x = P[(idx >> 1) * 4 + (idx & 1)];
        const float y = P[(idx >> 1) * 4 + 2 + (idx & 1)];
        rx = wrap1(x - x0);
        ry = wrap1(y - y0);
    }
    __shared__ float sx[64], sy[64];
    sx[tid] = rx; sy[tid] = ry;
    __syncthreads();
    if (tid == 0) {
        float mnx = 0, mxx = 0, mny = 0, mxy = 0;
        for (int t = 1; t < 64; ++t) {
            mnx = fminf(mnx, sx[t]); mxx = fmaxf(mxx, sx[t]);
            mny = fminf(mny, sy[t]); mxy = fmaxf(mxy, sy[t]);
        }
        const float4 bb = make_float4(x0 + 0.5f * (mnx + mxx),
                                      y0 + 0.5f * (mny + mxy),
                                      0.5f * (mxx - mnx),
                                      0.5f * (mxy - mny));
        if (b < NCHUNK) g_bboxJ[b] = bb;
        else            g_bboxI[b - NCHUNK] = bb;
    }
}

// ---------------- k1: main culled O(N^2) pass ----------------
template<bool SEP>
__device__ __forceinline__ void chunk_body(
    int c, u64 nxi2, u64 nyi2,
    u64 C2, u64 nC2, u64 nOne2, u64 half2, u64 sep2c, u64 perc2c,
    u64& Sx2, u64& Sy2, u64& Px2, u64& Py2, u64& Vx2, u64& Vy2, u64& Cn2)
{
    const ulonglong2* __restrict__ pp = (const ulonglong2*)g_pos4 + c * (CHUNK / 2);
    const ulonglong2* __restrict__ vv = (const ulonglong2*)g_vel4 + c * (CHUNK / 2);
    #pragma unroll 8
    for (int jj = 0; jj < CHUNK / 2; ++jj) {
        const ulonglong2 pj = pp[jj];     // (xA,xB | yA,yB), one LDG.128
        const ulonglong2 vj = vv[jj];

        const u64 dx2 = f2add(pj.x, nxi2);
        const u64 rx  = f2add(f2add(dx2, C2), nC2);      // rint(dx) exact
        const u64 dwx = f2fma(rx, nOne2, dx2);            // wrapped diff
        const u64 dy2 = f2add(pj.y, nyi2);
        const u64 ry  = f2add(f2add(dy2, C2), nC2);
        const u64 dwy = f2fma(ry, nOne2, dy2);

        const u64 d2 = f2fma(dwy, dwy, f2mul(dwx, dwx));
        const u64 mp = f2mask(f2fma(d2, nOne2, perc2c), half2);

        Px2 = f2fma(dwx, mp, Px2);
        Py2 = f2fma(dwy, mp, Py2);
        Vx2 = f2fma(vj.x, mp, Vx2);
        Vy2 = f2fma(vj.y, mp, Vy2);
        Cn2 = f2add(Cn2, mp);
        if (SEP) {
            const u64 ms = f2mask(f2fma(d2, nOne2, sep2c), half2);
            Sx2 = f2fma(dwx, ms, Sx2);
            Sy2 = f2fma(dwy, ms, Sy2);
        }
    }
}

__global__ __launch_bounds__(256)
void k1_pairs()
{
    const int lane = threadIdx.x & 31;
    const int wid  = blockIdx.x * 8 + (threadIdx.x >> 5);  // 0..4095
    const int g    = wid >> 4;     // i-tile 0..255
    const int s    = wid & 15;     // slot 0..15
    const int i    = g * 32 + lane;

    const float* P = (const float*)g_pos4;
    const float pix = P[(i >> 1) * 4 + (i & 1)];
    const float piy = P[(i >> 1) * 4 + 2 + (i & 1)];

    const u64 nxi2   = pack2(-pix, -pix);
    const u64 nyi2   = pack2(-piy, -piy);
    const u64 C2     = pack2( MAGIC,  MAGIC);
    const u64 nC2    = pack2(-MAGIC, -MAGIC);
    const u64 nOne2  = pack2(-1.0f, -1.0f);
    const u64 half2  = pack2(0.5f, 0.5f);
    const u64 sep2c  = pack2(SEP2F, SEP2F);
    const u64 perc2c = pack2(PERC2F, PERC2F);

    u64 Sx2 = 0, Sy2 = 0, Px2 = 0, Py2 = 0, Vx2 = 0, Vy2 = 0, Cn2 = 0;

    const float4 bi = g_bboxI[g];

    #pragma unroll
    for (int k = 0; k < KPER; ++k) {
        const int c = s + (k << 4);
        const float4 bj = g_bboxJ[c];
        // conservative toroidal box gap (warp-uniform)
        const float gx = fmaxf(0.0f, fabsf(wrap1(bi.x - bj.x)) - bi.z - bj.z - 1e-5f);
        const float gy = fmaxf(0.0f, fabsf(wrap1(bi.y - bj.y)) - bi.w - bj.w - 1e-5f);
        const float gap2 = gx * gx + gy * gy;
        if (gap2 > PERC2F) continue;           // whole chunk contributes exact zeros
        if (gap2 > SEP2F)
            chunk_body<false>(c, nxi2, nyi2, C2, nC2, nOne2, half2, sep2c, perc2c,
                              Sx2, Sy2, Px2, Py2, Vx2, Vy2, Cn2);
        else
            chunk_body<true >(c, nxi2, nyi2, C2, nC2, nOne2, half2, sep2c, perc2c,
                              Sx2, Sy2, Px2, Py2, Vx2, Vy2, Cn2);
    }

    float a, b;
    const int bix = s * NB + i;
    unpack2(Sx2, a, b);  g_part[0 * NSLOT * NB + bix] = a + b;
    unpack2(Sy2, a, b);  g_part[1 * NSLOT * NB + bix] = a + b;
    unpack2(Px2, a, b);  g_part[2 * NSLOT * NB + bix] = a + b;
    unpack2(Py2, a, b);  g_part[3 * NSLOT * NB + bix] = a + b;
    unpack2(Vx2, a, b);  g_part[4 * NSLOT * NB + bix] = a + b;
    unpack2(Vy2, a, b);  g_part[5 * NSLOT * NB + bix] = a + b;
    unpack2(Cn2, a, b);  g_part[6 * NSLOT * NB + bix] = a + b;
}

// ---------------- k2: reduce + epilogue (scatter to original order) ----------------
__global__ void k2_finalize(const float2* __restrict__ vel,
                            const float2* __restrict__ noise,
                            const float*  __restrict__ w_sep,
                            const float*  __restrict__ w_ali,
                            const float*  __restrict__ w_coh,
                            const float*  __restrict__ w_ns,
                            float2*       __restrict__ out)
{
    const int i = blockIdx.x * 256 + threadIdx.x;   // sorted index

    float s7[7];
    #pragma unroll
    for (int comp = 0; comp < 7; ++comp) {
        const float* p = g_part + (size_t)comp * NSLOT * NB + i;
        float acc = 0.0f;
        #pragma unroll
        for (int sl = 0; sl < NSLOT; ++sl) acc += p[(size_t)sl * NB];
        s7[comp] = acc;
    }

    const float Sx = s7[0], Sy = s7[1], Px = s7[2], Py = s7[3];
    const float Vx = s7[4], Vy = s7[5];
    const float C  = s7[6] - 1.0f;            // remove self

    const int orig = g_orig[i];
    const float2 vi = vel[orig];
    const float2 nz = noise[orig];

    float nrm = sqrtf(Sx * Sx + Sy * Sy);
    float inv = 1.0f / fmaxf(nrm, EPSF);
    const float sepx = -Sx * inv;
    const float sepy = -Sy * inv;

    const float invC = 1.0f / C;

    const float avx = (Vx - vi.x) * invC - vi.x;
    const float avy = (Vy - vi.y) * invC - vi.y;
    nrm = sqrtf(avx * avx + avy * avy);
    inv = 1.0f / fmaxf(nrm, EPSF);
    const float alix = avx * inv;
    const float aliy = avy * inv;

    const float cx = Px * invC;
    const float cy = Py * invC;
    nrm = sqrtf(cx * cx + cy * cy);
    inv = 1.0f / fmaxf(nrm, EPSF);
    const float cohx = cx * inv;
    const float cohy = cy * inv;

    const float ws = *w_sep;
    const float wa = *w_ali;
    const float wc = *w_coh;
    const float wn = *w_ns;

    float ax = ws * sepx + wa * alix + wc * cohx + wn * nz.x;
    float ay = ws * sepy + wa * aliy + wc * cohy + wn * nz.y;

    nrm = sqrtf(ax * ax + ay * ay);
    if (nrm > 1.0f) {
        const float sc = 1.0f / fmaxf(nrm, EPSF);
        ax *= sc;
        ay *= sc;
    }

    out[orig] = make_float2(ax, ay);
}

extern "C" void kernel_launch(void* const* d_in, const int* in_sizes, int n_in,
                              void* d_out, int out_size)
{
    const float2* pos   = (const float2*)d_in[0];
    const float2* vel   = (const float2*)d_in[1];
    const float2* noise = (const float2*)d_in[2];
    const float*  wsep  = (const float*)d_in[3];
    const float*  wali  = (const float*)d_in[4];
    const float*  wcoh  = (const float*)d_in[5];
    const float*  wns   = (const float*)d_in[6];
    float2* out = (float2*)d_out;

    kA_cells  <<<32, 256>>>(pos);
    kB_prefix <<<1, 64>>>();
    kC_scatter<<<32, 256>>>(pos, vel);
    kD_bbox   <<<NCHUNK + NTILE, 64>>>();
    k1_pairs  <<<512, 256>>>();
    k2_finalize<<<32, 256>>>(vel, noise, wsep, wali, wcoh, wns, out);
}

// round 5
// speedup vs baseline: 1.0513x; 1.0513x over previous
#include <cuda_runtime.h>

// BoidPolicy: all-pairs boids on a unit torus, N=8192, out acc [N,2] f32.
//
// Pipeline (graph-capturable, allocation-free):
//  kA: cell ids (8x8 grid), stable in-warp ranks, per-group histograms
//  kB: prefix sums -> scatter offsets
//  kC: scatter into sorted packed SoA (float4 = xA,xB,yA,yB per j-pair) + orig idx
//  kD: toroidal bboxes for the 128 j-chunks (warp-per-chunk shuffle reduce)
//  k1: one block per 32-i tile: bbox cull -> compact live-chunk list ->
//      warps stride the live list (balanced) -> smem reduce -> inline epilogue

#define NB      8192
#define NCELL   64            // 8x8 cells
#define NGRP    (NB / 32)     // 256
#define CHUNK   64
#define NCHUNK  (NB / CHUNK)  // 128
#define NTILE   (NB / 32)     // 256

#define SEP2F   4e-4f
#define PERC2F  0.04f
#define EPSF    1e-8f
#define MAGIC   12582912.0f   // 1.5 * 2^23
#define FULLM   0xffffffffu

typedef unsigned long long u64;

__device__ float4 g_pos4[NB / 2];     // sorted packed (xA,xB,yA,yB)
__device__ float4 g_vel4[NB / 2];
__device__ int    g_orig[NB];
__device__ int    g_cellid[NB];
__device__ int    g_lrank[NB];
__device__ int    g_cnt[NGRP * NCELL];
__device__ int    g_off[NGRP * NCELL];
__device__ float4 g_bboxJ[NCHUNK];    // (cx,cy,hx,hy)

__device__ __forceinline__ u64 pack2(float lo, float hi) {
    u64 r; asm("mov.b64 %0,{%1,%2};" : "=l"(r) : "f"(lo), "f"(hi)); return r;
}
__device__ __forceinline__ void unpack2(u64 v, float& lo, float& hi) {
    asm("mov.b64 {%0,%1},%2;" : "=f"(lo), "=f"(hi) : "l"(v));
}
__device__ __forceinline__ u64 f2add(u64 a, u64 b) {
    u64 d; asm("add.rn.f32x2 %0,%1,%2;" : "=l"(d) : "l"(a), "l"(b)); return d;
}
__device__ __forceinline__ u64 f2mul(u64 a, u64 b) {
    u64 d; asm("mul.rn.f32x2 %0,%1,%2;" : "=l"(d) : "l"(a), "l"(b)); return d;
}
__device__ __forceinline__ u64 f2fma(u64 a, u64 b, u64 c) {
    u64 d; asm("fma.rn.f32x2 %0,%1,%2,%3;" : "=l"(d) : "l"(a), "l"(b), "l"(c)); return d;
}
// per-half: (t >= 0) ? 1.0f : 0.0f  (exact: copysign(0.5,t)+0.5)
__device__ __forceinline__ u64 f2mask(u64 t, u64 half2) {
    u64 s = (t & 0x8000000080000000ULL) | 0x3F0000003F000000ULL;
    return f2add(s, half2);
}
__device__ __forceinline__ float wrap1(float d) { return d - rintf(d); }
__device__ __forceinline__ float getX(const float* P, int idx) {
    return P[(idx >> 1) * 4 + (idx & 1)];
}
__device__ __forceinline__ float getY(const float* P, int idx) {
    return P[(idx >> 1) * 4 + 2 + (idx & 1)];
}

// ---------------- kA: cells + stable local ranks + histograms ----------------
__global__ void kA_cells(const float2* __restrict__ pos)
{
    __shared__ int scnt[8][NCELL];
    const int tid = threadIdx.x;
    for (int t = tid; t < 8 * NCELL; t += 256) ((int*)scnt)[t] = 0;
    __syncthreads();

    const int w    = tid >> 5;
    const int lane = tid & 31;
    const int e    = (blockIdx.x * 8 + w) * 32 + lane;
    const float2 p = pos[e];
    int cx = (int)(p.x * 8.0f); cx = cx < 0 ? 0 : (cx > 7 ? 7 : cx);
    int cy = (int)(p.y * 8.0f); cy = cy < 0 ? 0 : (cy > 7 ? 7 : cy);
    const int cell = cy * 8 + cx;

    const unsigned peers = __match_any_sync(FULLM, cell);
    g_cellid[e] = cell;
    g_lrank[e]  = __popc(peers & ((1u << lane) - 1u));
    if ((__ffs(peers) - 1) == lane)
        scnt[w][cell] = __popc(peers);
    __syncthreads();

    for (int t = tid; t < 8 * NCELL; t += 256)
        g_cnt[blockIdx.x * 8 * NCELL + t] = ((int*)scnt)[t];
}

// ---------------- kB: prefix sums -> scatter offsets ----------------
__global__ void kB_prefix()
{
    const int c = threadIdx.x;   // 64 threads, one per cell
    int run = 0;
    for (int g = 0; g < NGRP; ++g) {
        const int v = g_cnt[g * NCELL + c];
        g_off[g * NCELL + c] = run;
        run += v;
    }
    __shared__ int tot[NCELL];
    tot[c] = run;
    __syncthreads();
    int base = 0;
    for (int c2 = 0; c2 < c; ++c2) base += tot[c2];
    for (int g = 0; g < NGRP; ++g) g_off[g * NCELL + c] += base;
}

// ---------------- kC: scatter into sorted packed SoA ----------------
__global__ void kC_scatter(const float2* __restrict__ pos,
                           const float2* __restrict__ vel)
{
    const int e   = blockIdx.x * 256 + threadIdx.x;
    const int c   = g_cellid[e];
    const int dst = g_off[(e >> 5) * NCELL + c] + g_lrank[e];
    const float2 p = pos[e];
    const float2 v = vel[e];
    float* P = (float*)g_pos4;
    float* V = (float*)g_vel4;
    const int b = (dst >> 1) * 4 + (dst & 1);
    P[b] = p.x;  P[b + 2] = p.y;
    V[b] = v.x;  V[b + 2] = v.y;
    g_orig[dst] = e;
}

// ---------------- kD: j-chunk bboxes, one warp per chunk ----------------
__global__ void kD_bbox()     // grid = 64, block = 64 (2 warps)
{
    const int c    = blockIdx.x * 2 + (threadIdx.x >> 5);
    const int lane = threadIdx.x & 31;
    const int base = c * CHUNK;
    const float* P = (const float*)g_pos4;

    const float x0 = getX(P, base);
    const float y0 = getY(P, base);

    const int iA = base + lane;
    const int iB = base + lane + 32;
    const float rxA = wrap1(getX(P, iA) - x0), ryA = wrap1(getY(P, iA) - y0);
    const float rxB = wrap1(getX(P, iB) - x0), ryB = wrap1(getY(P, iB) - y0);

    float mnx = fminf(rxA, rxB), mxx = fmaxf(rxA, rxB);
    float mny = fminf(ryA, ryB), mxy = fmaxf(ryA, ryB);
    #pragma unroll
    for (int o = 16; o; o >>= 1) {
        mnx = fminf(mnx, __shfl_xor_sync(FULLM, mnx, o));
        mxx = fmaxf(mxx, __shfl_xor_sync(FULLM, mxx, o));
        mny = fminf(mny, __shfl_xor_sync(FULLM, mny, o));
        mxy = fmaxf(mxy, __shfl_xor_sync(FULLM, mxy, o));
    }
    if (lane == 0)
        g_bboxJ[c] = make_float4(x0 + 0.5f * (mnx + mxx),
                                 y0 + 0.5f * (mny + mxy),
                                 0.5f * (mxx - mnx),
                                 0.5f * (mxy - mny));
}

// ---------------- k1: cull + pairs + reduce + epilogue ----------------
template<bool SEP>
__device__ __forceinline__ void chunk_body(
    int c, u64 nxi2, u64 nyi2,
    u64 C2, u64 nC2, u64 nOne2, u64 half2, u64 sep2c, u64 perc2c,
    u64& Sx2, u64& Sy2, u64& Px2, u64& Py2, u64& Vx2, u64& Vy2, u64& Cn2)
{
    const ulonglong2* __restrict__ pp = (const ulonglong2*)g_pos4 + c * (CHUNK / 2);
    const ulonglong2* __restrict__ vv = (const ulonglong2*)g_vel4 + c * (CHUNK / 2);
    #pragma unroll 8
    for (int jj = 0; jj < CHUNK / 2; ++jj) {
        const ulonglong2 pj = pp[jj];   // (xA,xB | yA,yB), one LDG.128, warp-uniform
        const ulonglong2 vj = vv[jj];

        const u64 dx2 = f2add(pj.x, nxi2);
        const u64 rx  = f2add(f2add(dx2, C2), nC2);   // rint(dx), exact
        const u64 dwx = f2fma(rx, nOne2, dx2);         // wrapped diff
        const u64 dy2 = f2add(pj.y, nyi2);
        const u64 ry  = f2add(f2add(dy2, C2), nC2);
        const u64 dwy = f2fma(ry, nOne2, dy2);

        const u64 d2 = f2fma(dwy, dwy, f2mul(dwx, dwx));
        const u64 mp = f2mask(f2fma(d2, nOne2, perc2c), half2);

        Px2 = f2fma(dwx, mp, Px2);
        Py2 = f2fma(dwy, mp, Py2);
        Vx2 = f2fma(vj.x, mp, Vx2);
        Vy2 = f2fma(vj.y, mp, Vy2);
        Cn2 = f2add(Cn2, mp);
        if (SEP) {
            const u64 ms = f2mask(f2fma(d2, nOne2, sep2c), half2);
            Sx2 = f2fma(dwx, ms, Sx2);
            Sy2 = f2fma(dwy, ms, Sy2);
        }
    }
}

__global__ __launch_bounds__(256)
void k1_main(const float2* __restrict__ vel,
             const float2* __restrict__ noise,
             const float*  __restrict__ w_sep,
             const float*  __restrict__ w_ali,
             const float*  __restrict__ w_coh,
             const float*  __restrict__ w_ns,
             float2*       __restrict__ out)
{
    __shared__ int   s_live[NCHUNK];
    __shared__ int   s_wbase[4];
    __shared__ int   s_cnt;
    __shared__ float red[8][32][9];

    const int tid  = threadIdx.x;
    const int lane = tid & 31;
    const int w    = tid >> 5;
    const int g    = blockIdx.x;          // i-tile
    const int i    = g * 32 + lane;

    const float* P = (const float*)g_pos4;
    const float pix = getX(P, i);
    const float piy = getY(P, i);

    // --- tile bbox (every warp computes identical copy via shuffles) ---
    const float x0 = __shfl_sync(FULLM, pix, 0);
    const float y0 = __shfl_sync(FULLM, piy, 0);
    const float rx = wrap1(pix - x0);
    const float ry = wrap1(piy - y0);
    float mnx = rx, mxx = rx, mny = ry, mxy = ry;
    #pragma unroll
    for (int o = 16; o; o >>= 1) {
        mnx = fminf(mnx, __shfl_xor_sync(FULLM, mnx, o));
        mxx = fmaxf(mxx, __shfl_xor_sync(FULLM, mxx, o));
        mny = fminf(mny, __shfl_xor_sync(FULLM, mny, o));
        mxy = fmaxf(mxy, __shfl_xor_sync(FULLM, mxy, o));
    }
    const float bcx = x0 + 0.5f * (mnx + mxx);
    const float bcy = y0 + 0.5f * (mny + mxy);
    const float bhx = 0.5f * (mxx - mnx);
    const float bhy = 0.5f * (mxy - mny);

    // --- stage 1: cull + compact live-chunk list (warps 0..3, chunk = tid) ---
    if (w < 4) {
        const float4 bj = g_bboxJ[tid];
        const float gx = fmaxf(0.0f, fabsf(wrap1(bcx - bj.x)) - bhx - bj.z - 1e-5f);
        const float gy = fmaxf(0.0f, fabsf(wrap1(bcy - bj.y)) - bhy - bj.w - 1e-5f);
        const float gap2 = gx * gx + gy * gy;
        const bool live = (gap2 <= PERC2F);
        const bool sep  = (gap2 <= SEP2F);
        const unsigned m = __ballot_sync(FULLM, live);
        if (lane == 0) s_wbase[w] = __popc(m);
        __syncwarp();
        // keep m, live, sep in regs across the block sync
        __syncthreads();
        if (tid == 0) {
            int run = 0;
            #pragma unroll
            for (int k = 0; k < 4; ++k) { const int v = s_wbase[k]; s_wbase[k] = run; run += v; }
            s_cnt = run;
        }
        __syncthreads();
        if (live) {
            const int pos = s_wbase[w] + __popc(m & ((1u << lane) - 1u));
            s_live[pos] = tid | (sep ? 0x10000 : 0);
        }
    } else {
        __syncthreads();
        __syncthreads();
    }
    __syncthreads();
    const int nlive = s_cnt;

    // --- stage 2: balanced strided walk over live chunks ---
    const u64 nxi2   = pack2(-pix, -pix);
    const u64 nyi2   = pack2(-piy, -piy);
    const u64 C2     = pack2( MAGIC,  MAGIC);
    const u64 nC2    = pack2(-MAGIC, -MAGIC);
    const u64 nOne2  = pack2(-1.0f, -1.0f);
    const u64 half2  = pack2(0.5f, 0.5f);
    const u64 sep2c  = pack2(SEP2F, SEP2F);
    const u64 perc2c = pack2(PERC2F, PERC2F);

    u64 Sx2 = 0, Sy2 = 0, Px2 = 0, Py2 = 0, Vx2 = 0, Vy2 = 0, Cn2 = 0;

    for (int k = w; k < nlive; k += 8) {
        const int e = s_live[k];
        const int c = e & 0xFFFF;
        if (e & 0x10000)
            chunk_body<true >(c, nxi2, nyi2, C2, nC2, nOne2, half2, sep2c, perc2c,
                              Sx2, Sy2, Px2, Py2, Vx2, Vy2, Cn2);
        else
            chunk_body<false>(c, nxi2, nyi2, C2, nC2, nOne2, half2, sep2c, perc2c,
                              Sx2, Sy2, Px2, Py2, Vx2, Vy2, Cn2);
    }

    // --- stage 3: smem reduce (deterministic) + epilogue ---
    float a, b;
    unpack2(Sx2, a, b);  red[w][lane][0] = a + b;
    unpack2(Sy2, a, b);  red[w][lane][1] = a + b;
    unpack2(Px2, a, b);  red[w][lane][2] = a + b;
    unpack2(Py2, a, b);  red[w][lane][3] = a + b;
    unpack2(Vx2, a, b);  red[w][lane][4] = a + b;
    unpack2(Vy2, a, b);  red[w][lane][5] = a + b;
    unpack2(Cn2, a, b);  red[w][lane][6] = a + b;
    __syncthreads();

    if (tid < 32) {
        float s7[7];
        #pragma unroll
        for (int comp = 0; comp < 7; ++comp) {
            float acc = 0.0f;
            #pragma unroll
            for (int sg = 0; sg < 8; ++sg) acc += red[sg][tid][comp];
            s7[comp] = acc;
        }

        const float Sx = s7[0], Sy = s7[1], Px = s7[2], Py = s7[3];
        const float Vx = s7[4], Vy = s7[5];
        const float C  = s7[6] - 1.0f;     // remove self

        const int orig = g_orig[g * 32 + tid];
        const float2 vi = vel[orig];
        const float2 nz = noise[orig];

        float nrm = sqrtf(Sx * Sx + Sy * Sy);
        float inv = 1.0f / fmaxf(nrm, EPSF);
        const float sepx = -Sx * inv;
        const float sepy = -Sy * inv;

        const float invC = 1.0f / C;

        const float avx = (Vx - vi.x) * invC - vi.x;
        const float avy = (Vy - vi.y) * invC - vi.y;
        nrm = sqrtf(avx * avx + avy * avy);
        inv = 1.0f / fmaxf(nrm, EPSF);
        const float alix = avx * inv;
        const float aliy = avy * inv;

        const float cx = Px * invC;
        const float cy = Py * invC;
        nrm = sqrtf(cx * cx + cy * cy);
        inv = 1.0f / fmaxf(nrm, EPSF);
        const float cohx = cx * inv;
        const float cohy = cy * inv;

        const float ws = *w_sep;
        const float wa = *w_ali;
        const float wc = *w_coh;
        const float wn = *w_ns;

        float ax = ws * sepx + wa * alix + wc * cohx + wn * nz.x;
        float ay = ws * sepy + wa * aliy + wc * cohy + wn * nz.y;

        nrm = sqrtf(ax * ax + ay * ay);
        if (nrm > 1.0f) {
            const float sc = 1.0f / fmaxf(nrm, EPSF);
            ax *= sc;
            ay *= sc;
        }

        out[orig] = make_float2(ax, ay);
    }
}

extern "C" void kernel_launch(void* const* d_in, const int* in_sizes, int n_in,
                              void* d_out, int out_size)
{
    const float2* pos   = (const float2*)d_in[0];
    const float2* vel   = (const float2*)d_in[1];
    const float2* noise = (const float2*)d_in[2];
    const float*  wsep  = (const float*)d_in[3];
    const float*  wali  = (const float*)d_in[4];
    const float*  wcoh  = (const float*)d_in[5];
    const float*  wns   = (const float*)d_in[6];
    float2* out = (float2*)d_out;

    kA_cells  <<<32, 256>>>(pos);
    kB_prefix <<<1, 64>>>();
    kC_scatter<<<32, 256>>>(pos, vel);
    kD_bbox   <<<NCHUNK / 2, 64>>>();
    k1_main   <<<NTILE, 256>>>(vel, noise, wsep, wali, wcoh, wns, out);
}

// round 6
// speedup vs baseline: 1.5168x; 1.4428x over previous
#include <cuda_runtime.h>

// BoidPolicy: all-pairs boids on a unit torus, N=8192, out acc [N,2] f32.
//
// Pipeline (graph-capturable, allocation-free, 4 launches):
//  kA: 16x16 cell ids (snake row order) + per-block smem-atomic ranks + histograms
//  kB: prefix sums -> scatter offsets (single block)
//  kC: scatter into sorted packed SoA (float4 = xA,xB,yA,yB per j-pair) + cell byte + orig idx
//  k1: per 32-i tile: cull 256 static cell rects vs tile bbox -> pair-level live mask
//      -> block-compacted u16 pair list -> warps stride list (balanced)
//      -> f32x2 pair math -> smem reduce -> inline epilogue

#define NB      8192
#define GCD     16
#define NCELL   256
#define NBLKA   32
#define NTILE   256

#define SEP2F   4e-4f
#define PERC2F  0.04f
#define EPSF    1e-8f
#define MAGIC   12582912.0f   // 1.5 * 2^23
#define FULLM   0xffffffffu

typedef unsigned long long u64;
typedef unsigned short u16;

__device__ float4 g_pos4[NB / 2];       // sorted packed (xA,xB,yA,yB)
__device__ float4 g_vel4[NB / 2];
__device__ int    g_orig[NB];
__device__ uint4  g_scellv[NB / 16];    // sorted cell id per boid (bytes), 16B-aligned
__device__ int    g_cellid[NB];
__device__ int    g_lrank[NB];
__device__ int    g_cnt[NBLKA * NCELL];
__device__ int    g_off[NBLKA * NCELL];

__device__ __forceinline__ u64 pack2(float lo, float hi) {
    u64 r; asm("mov.b64 %0,{%1,%2};" : "=l"(r) : "f"(lo), "f"(hi)); return r;
}
__device__ __forceinline__ void unpack2(u64 v, float& lo, float& hi) {
    asm("mov.b64 {%0,%1},%2;" : "=f"(lo), "=f"(hi) : "l"(v));
}
__device__ __forceinline__ u64 f2add(u64 a, u64 b) {
    u64 d; asm("add.rn.f32x2 %0,%1,%2;" : "=l"(d) : "l"(a), "l"(b)); return d;
}
__device__ __forceinline__ u64 f2mul(u64 a, u64 b) {
    u64 d; asm("mul.rn.f32x2 %0,%1,%2;" : "=l"(d) : "l"(a), "l"(b)); return d;
}
__device__ __forceinline__ u64 f2fma(u64 a, u64 b, u64 c) {
    u64 d; asm("fma.rn.f32x2 %0,%1,%2,%3;" : "=l"(d) : "l"(a), "l"(b), "l"(c)); return d;
}
// per-half: (t >= 0) ? 1.0f : 0.0f  (exact: copysign(0.5,t)+0.5)
__device__ __forceinline__ u64 f2mask(u64 t, u64 half2) {
    u64 s = (t & 0x8000000080000000ULL) | 0x3F0000003F000000ULL;
    return f2add(s, half2);
}
__device__ __forceinline__ float wrap1(float d) { return d - rintf(d); }
__device__ __forceinline__ float getX(const float* P, int idx) {
    return P[(idx >> 1) * 4 + (idx & 1)];
}
__device__ __forceinline__ float getY(const float* P, int idx) {
    return P[(idx >> 1) * 4 + 2 + (idx & 1)];
}

// ---------------- kA: cell ids + ranks + per-block histograms ----------------
__global__ void kA_cells(const float2* __restrict__ pos)
{
    __shared__ int hist[NCELL];
    const int tid = threadIdx.x;
    hist[tid] = 0;
    __syncthreads();

    const int e = blockIdx.x * 256 + tid;
    const float2 p = pos[e];
    int cx = (int)(p.x * 16.0f); cx = cx < 0 ? 0 : (cx > 15 ? 15 : cx);
    int cy = (int)(p.y * 16.0f); cy = cy < 0 ? 0 : (cy > 15 ? 15 : cy);
    const int lx   = (cy & 1) ? (15 - cx) : cx;       // snake order
    const int cell = (cy << 4) | lx;

    const int r = atomicAdd(&hist[cell], 1);
    g_cellid[e] = cell;
    g_lrank[e]  = r;
    __syncthreads();

    g_cnt[blockIdx.x * NCELL + tid] = hist[tid];
}

// ---------------- kB: prefix sums -> scatter offsets (1 block, 256 thr) ----------------
__global__ void kB_prefix()
{
    const int c = threadIdx.x;          // one cell per thread
    int run = 0;
    for (int g = 0; g < NBLKA; ++g) {
        const int v = g_cnt[g * NCELL + c];
        g_off[g * NCELL + c] = run;
        run += v;
    }
    // exclusive scan of per-cell totals across 256 threads
    __shared__ int wsum[8];
    __shared__ int wbase[8];
    const int lane = c & 31, w = c >> 5;
    int s = run;
    #pragma unroll
    for (int o = 1; o < 32; o <<= 1) {
        const int t = __shfl_up_sync(FULLM, s, o);
        if (lane >= o) s += t;
    }
    if (lane == 31) wsum[w] = s;
    __syncthreads();
    if (c == 0) {
        int acc = 0;
        #pragma unroll
        for (int k = 0; k < 8; ++k) { wbase[k] = acc; acc += wsum[k]; }
    }
    __syncthreads();
    const int base = wbase[w] + s - run;   // exclusive prefix of this cell
    for (int g = 0; g < NBLKA; ++g) g_off[g * NCELL + c] += base;
}

// ---------------- kC: scatter into sorted packed SoA ----------------
__global__ void kC_scatter(const float2* __restrict__ pos,
                           const float2* __restrict__ vel)
{
    const int e    = blockIdx.x * 256 + threadIdx.x;
    const int cell = g_cellid[e];
    const int dst  = g_off[(e >> 8) * NCELL + cell] + g_lrank[e];
    const float2 p = pos[e];
    const float2 v = vel[e];
    float* P = (float*)g_pos4;
    float* V = (float*)g_vel4;
    const int b = (dst >> 1) * 4 + (dst & 1);
    P[b] = p.x;  P[b + 2] = p.y;
    V[b] = v.x;  V[b + 2] = v.y;
    g_orig[dst] = e;
    ((unsigned char*)g_scellv)[dst] = (unsigned char)cell;
}

// ---------------- k1: cull + compact pairs + pair math + epilogue ----------------
__global__ __launch_bounds__(256)
void k1_main(const float2* __restrict__ vel,
             const float2* __restrict__ noise,
             const float*  __restrict__ w_sep,
             const float*  __restrict__ w_ali,
             const float*  __restrict__ w_coh,
             const float*  __restrict__ w_ns,
             float2*       __restrict__ out)
{
    __shared__ unsigned s_mask[8];        // 256-bit live-cell mask
    __shared__ int      s_scan[8];
    __shared__ int      s_total;
    __shared__ u16      s_pairs[NB / 2];  // live pair indices (worst case all)
    __shared__ float    red[8][32][8];

    const int tid  = threadIdx.x;
    const int lane = tid & 31;
    const int w    = tid >> 5;
    const int g    = blockIdx.x;          // i-tile
    const int i    = g * 32 + lane;

    const float* P = (const float*)g_pos4;
    const float pix = getX(P, i);
    const float piy = getY(P, i);

    // --- tile bbox (each warp computes an identical copy via shuffles) ---
    const float x0 = __shfl_sync(FULLM, pix, 0);
    const float y0 = __shfl_sync(FULLM, piy, 0);
    const float rx = wrap1(pix - x0);
    const float ry = wrap1(piy - y0);
    float mnx = rx, mxx = rx, mny = ry, mxy = ry;
    #pragma unroll
    for (int o = 16; o; o >>= 1) {
        mnx = fminf(mnx, __shfl_xor_sync(FULLM, mnx, o));
        mxx = fmaxf(mxx, __shfl_xor_sync(FULLM, mxx, o));
        mny = fminf(mny, __shfl_xor_sync(FULLM, mny, o));
        mxy = fmaxf(mxy, __shfl_xor_sync(FULLM, mxy, o));
    }
    const float bcx = x0 + 0.5f * (mnx + mxx);
    const float bcy = y0 + 0.5f * (mny + mxy);
    const float bhx = 0.5f * (mxx - mnx);
    const float bhy = 0.5f * (mxy - mny);

    // --- cull: thread tid tests static rect of cell tid ---
    {
        const int cy = tid >> 4;
        const int lx = tid & 15;
        const int cx = (cy & 1) ? (15 - lx) : lx;
        const float ccx = (cx + 0.5f) * (1.0f / 16.0f);
        const float ccy = (cy + 0.5f) * (1.0f / 16.0f);
        const float gx = fmaxf(0.0f, fabsf(wrap1(bcx - ccx)) - bhx - (1.0f / 32.0f) - 1e-5f);
        const float gy = fmaxf(0.0f, fabsf(wrap1(bcy - ccy)) - bhy - (1.0f / 32.0f) - 1e-5f);
        const bool live = (gx * gx + gy * gy) <= PERC2F;
        const unsigned m = __ballot_sync(FULLM, live);
        if (lane == 0) s_mask[w] = m;
    }
    __syncthreads();

    // --- pair-level liveness + block compaction ---
    // thread t owns pairs [16t, 16t+16) = boids [32t, 32t+32)
    unsigned pl = 0;
    {
        const uint4 c0 = g_scellv[tid * 2];
        const uint4 c1 = g_scellv[tid * 2 + 1];
        const unsigned cw[8] = {c0.x, c0.y, c0.z, c0.w, c1.x, c1.y, c1.z, c1.w};
        #pragma unroll
        for (int q = 0; q < 8; ++q) {
            const unsigned word = cw[q];
            #pragma unroll
            for (int h = 0; h < 2; ++h) {
                const unsigned ca = (word >> (h * 16)) & 0xffu;
                const unsigned cb = (word >> (h * 16 + 8)) & 0xffu;
                const unsigned lv = ((s_mask[ca >> 5] >> (ca & 31)) |
                                     (s_mask[cb >> 5] >> (cb & 31))) & 1u;
                pl |= lv << (q * 2 + h);
            }
        }
    }
    const int cntp = __popc(pl);
    int s = cntp;
    #pragma unroll
    for (int o = 1; o < 32; o <<= 1) {
        const int t = __shfl_up_sync(FULLM, s, o);
        if (lane >= o) s += t;
    }
    if (lane == 31) s_scan[w] = s;
    __syncthreads();
    if (tid == 0) {
        int acc = 0;
        #pragma unroll
        for (int k = 0; k < 8; ++k) { const int v = s_scan[k]; s_scan[k] = acc; acc += v; }
        s_total = acc;
    }
    __syncthreads();
    int ofs = s_scan[w] + s - cntp;
    unsigned m2 = pl;
    while (m2) {
        const int b = __ffs(m2) - 1;
        m2 &= m2 - 1;
        s_pairs[ofs++] = (u16)(tid * 16 + b);
    }
    __syncthreads();
    const int total = s_total;

    // --- main pair loop: warps stride the compacted list (balanced) ---
    const u64 nxi2   = pack2(-pix, -pix);
    const u64 nyi2   = pack2(-piy, -piy);
    const u64 C2     = pack2( MAGIC,  MAGIC);
    const u64 nC2    = pack2(-MAGIC, -MAGIC);
    const u64 nOne2  = pack2(-1.0f, -1.0f);
    const u64 half2  = pack2(0.5f, 0.5f);
    const u64 sep2c  = pack2(SEP2F, SEP2F);
    const u64 perc2c = pack2(PERC2F, PERC2F);

    u64 Sx2 = 0, Sy2 = 0, Px2 = 0, Py2 = 0, Vx2 = 0, Vy2 = 0, Cn2 = 0;

    const ulonglong2* __restrict__ PP = (const ulonglong2*)g_pos4;
    const ulonglong2* __restrict__ VV = (const ulonglong2*)g_vel4;

    for (int k = w; k < total; k += 8) {
        const int idx = s_pairs[k];           // warp-uniform -> LDS broadcast
        const ulonglong2 pj = PP[idx];        // one LDG.128, warp-uniform
        const ulonglong2 vj = VV[idx];

        const u64 dx2 = f2add(pj.x, nxi2);
        const u64 rxp = f2add(f2add(dx2, C2), nC2);   // rint(dx), exact
        const u64 dwx = f2fma(rxp, nOne2, dx2);        // wrapped diff
        const u64 dy2 = f2add(pj.y, nyi2);
        const u64 ryp = f2add(f2add(dy2, C2), nC2);
        const u64 dwy = f2fma(ryp, nOne2, dy2);

        const u64 d2 = f2fma(dwy, dwy, f2mul(dwx, dwx));
        const u64 mp = f2mask(f2fma(d2, nOne2, perc2c), half2);
        const u64 ms = f2mask(f2fma(d2, nOne2, sep2c),  half2);

        Px2 = f2fma(dwx, mp, Px2);
        Py2 = f2fma(dwy, mp, Py2);
        Vx2 = f2fma(vj.x, mp, Vx2);
        Vy2 = f2fma(vj.y, mp, Vy2);
        Cn2 = f2add(Cn2, mp);
        Sx2 = f2fma(dwx, ms, Sx2);
        Sy2 = f2fma(dwy, ms, Sy2);
    }

    // --- smem reduce (deterministic) + epilogue ---
    float a, b;
    unpack2(Sx2, a, b);  red[w][lane][0] = a + b;
    unpack2(Sy2, a, b);  red[w][lane][1] = a + b;
    unpack2(Px2, a, b);  red[w][lane][2] = a + b;
    unpack2(Py2, a, b);  red[w][lane][3] = a + b;
    unpack2(Vx2, a, b);  red[w][lane][4] = a + b;
    unpack2(Vy2, a, b);  red[w][lane][5] = a + b;
    unpack2(Cn2, a, b);  red[w][lane][6] = a + b;
    __syncthreads();

    if (tid < 32) {
        float s7[7];
        #pragma unroll
        for (int comp = 0; comp < 7; ++comp) {
            float acc = 0.0f;
            #pragma unroll
            for (int sg = 0; sg < 8; ++sg) acc += red[sg][tid][comp];
            s7[comp] = acc;
        }

        const float Sx = s7[0], Sy = s7[1], Px = s7[2], Py = s7[3];
        const float Vx = s7[4], Vy = s7[5];
        const float C  = s7[6] - 1.0f;       // remove self

        const int orig = g_orig[g * 32 + tid];
        const float2 vi = vel[orig];
        const float2 nz = noise[orig];

        float nrm = sqrtf(Sx * Sx + Sy * Sy);
        float inv = 1.0f / fmaxf(nrm, EPSF);
        const float sepx = -Sx * inv;
        const float sepy = -Sy * inv;

        const float invC = 1.0f / C;

        const float avx = (Vx - vi.x) * invC - vi.x;
        const float avy = (Vy - vi.y) * invC - vi.y;
        nrm = sqrtf(avx * avx + avy * avy);
        inv = 1.0f / fmaxf(nrm, EPSF);
        const float alix = avx * inv;
        const float aliy = avy * inv;

        const float cx2 = Px * invC;
        const float cy2 = Py * invC;
        nrm = sqrtf(cx2 * cx2 + cy2 * cy2);
        inv = 1.0f / fmaxf(nrm, EPSF);
        const float cohx = cx2 * inv;
        const float cohy = cy2 * inv;

        const float ws = *w_sep;
        const float wa = *w_ali;
        const float wc = *w_coh;
        const float wn = *w_ns;

        float ax = ws * sepx + wa * alix + wc * cohx + wn * nz.x;
        float ay = ws * sepy + wa * aliy + wc * cohy + wn * nz.y;

        nrm = sqrtf(ax * ax + ay * ay);
        if (nrm > 1.0f) {
            const float sc = 1.0f / fmaxf(nrm, EPSF);
            ax *= sc;
            ay *= sc;
        }

        out[orig] = make_float2(ax, ay);
    }
}

extern "C" void kernel_launch(void* const* d_in, const int* in_sizes, int n_in,
                              void* d_out, int out_size)
{
    const float2* pos   = (const float2*)d_in[0];
    const float2* vel   = (const float2*)d_in[1];
    const float2* noise = (const float2*)d_in[2];
    const float*  wsep  = (const float*)d_in[3];
    const float*  wali  = (const float*)d_in[4];
    const float*  wcoh  = (const float*)d_in[5];
    const float*  wns   = (const float*)d_in[6];
    float2* out = (float2*)d_out;

    kA_cells  <<<NBLKA, 256>>>(pos);
    kB_prefix <<<1, 256>>>();
    kC_scatter<<<NBLKA, 256>>>(pos, vel);
    k1_main   <<<NTILE, 256>>>(vel, noise, wsep, wali, wcoh, wns, out);
}

// round 7
// speedup vs baseline: 1.9524x; 1.2872x over previous
#include <cuda_runtime.h>

// BoidPolicy: all-pairs boids on a unit torus, N=8192, out acc [N,2] f32.
//
// Pipeline (graph-capturable, allocation-free, 4 launches):
//  kA: 16x16 cell ids (snake rows) + per-block smem-atomic ranks + histograms
//  kB: prefix sums -> scatter offsets (single block)
//  kC: scatter into sorted packed SoA (float4 = xA,xB,yA,yB per j-pair) + cell byte + orig idx
//  k1: per 32-i tile (512 threads): cull 256 cell rects vs tile bbox -> pair live mask
//      -> block-compacted u16 pair list -> 16 warps take contiguous segments,
//      unroll-4 with batched loads (MLP=8) -> f32x2 pair math -> reduce -> epilogue

#define NB      8192
#define NCELL   256
#define NBLKA   32
#define NTILE   256
#define TPB1    512
#define NWARP   16

#define SEP2F   4e-4f
#define PERC2F  0.04f
#define EPSF    1e-8f
#define MAGIC   12582912.0f   // 1.5 * 2^23
#define FULLM   0xffffffffu

typedef unsigned long long u64;
typedef unsigned short u16;

__device__ float4 g_pos4[NB / 2];       // sorted packed (xA,xB,yA,yB)
__device__ float4 g_vel4[NB / 2];
__device__ int    g_orig[NB];
__device__ uint4  g_scellv[NB / 16];    // sorted cell ids, 1 byte per boid
__device__ int    g_cellid[NB];
__device__ int    g_lrank[NB];
__device__ int    g_cnt[NBLKA * NCELL];
__device__ int    g_off[NBLKA * NCELL];

__device__ __forceinline__ u64 pack2(float lo, float hi) {
    u64 r; asm("mov.b64 %0,{%1,%2};" : "=l"(r) : "f"(lo), "f"(hi)); return r;
}
__device__ __forceinline__ void unpack2(u64 v, float& lo, float& hi) {
    asm("mov.b64 {%0,%1},%2;" : "=f"(lo), "=f"(hi) : "l"(v));
}
__device__ __forceinline__ u64 f2add(u64 a, u64 b) {
    u64 d; asm("add.rn.f32x2 %0,%1,%2;" : "=l"(d) : "l"(a), "l"(b)); return d;
}
__device__ __forceinline__ u64 f2mul(u64 a, u64 b) {
    u64 d; asm("mul.rn.f32x2 %0,%1,%2;" : "=l"(d) : "l"(a), "l"(b)); return d;
}
__device__ __forceinline__ u64 f2fma(u64 a, u64 b, u64 c) {
    u64 d; asm("fma.rn.f32x2 %0,%1,%2,%3;" : "=l"(d) : "l"(a), "l"(b), "l"(c)); return d;
}
// per-half: (t >= 0) ? 1.0f : 0.0f  (exact: copysign(0.5,t)+0.5)
__device__ __forceinline__ u64 f2mask(u64 t, u64 half2) {
    u64 s = (t & 0x8000000080000000ULL) | 0x3F0000003F000000ULL;
    return f2add(s, half2);
}
__device__ __forceinline__ float wrap1(float d) { return d - rintf(d); }
__device__ __forceinline__ float getX(const float* P, int idx) {
    return P[(idx >> 1) * 4 + (idx & 1)];
}
__device__ __forceinline__ float getY(const float* P, int idx) {
    return P[(idx >> 1) * 4 + 2 + (idx & 1)];
}

// ---------------- kA: cell ids + ranks + per-block histograms ----------------
__global__ void kA_cells(const float2* __restrict__ pos)
{
    __shared__ int hist[NCELL];
    const int tid = threadIdx.x;
    hist[tid] = 0;
    __syncthreads();

    const int e = blockIdx.x * 256 + tid;
    const float2 p = pos[e];
    int cx = (int)(p.x * 16.0f); cx = cx < 0 ? 0 : (cx > 15 ? 15 : cx);
    int cy = (int)(p.y * 16.0f); cy = cy < 0 ? 0 : (cy > 15 ? 15 : cy);
    const int lx   = (cy & 1) ? (15 - cx) : cx;       // snake order
    const int cell = (cy << 4) | lx;

    const int r = atomicAdd(&hist[cell], 1);
    g_cellid[e] = cell;
    g_lrank[e]  = r;
    __syncthreads();

    g_cnt[blockIdx.x * NCELL + tid] = hist[tid];
}

// ---------------- kB: prefix sums -> scatter offsets (1 block, 256 thr) ----------------
__global__ void kB_prefix()
{
    const int c = threadIdx.x;
    int run = 0;
    for (int g = 0; g < NBLKA; ++g) {
        const int v = g_cnt[g * NCELL + c];
        g_off[g * NCELL + c] = run;
        run += v;
    }
    __shared__ int wsum[8];
    __shared__ int wbase[8];
    const int lane = c & 31, w = c >> 5;
    int s = run;
    #pragma unroll
    for (int o = 1; o < 32; o <<= 1) {
        const int t = __shfl_up_sync(FULLM, s, o);
        if (lane >= o) s += t;
    }
    if (lane == 31) wsum[w] = s;
    __syncthreads();
    if (c == 0) {
        int acc = 0;
        #pragma unroll
        for (int k = 0; k < 8; ++k) { wbase[k] = acc; acc += wsum[k]; }
    }
    __syncthreads();
    const int base = wbase[w] + s - run;
    for (int g = 0; g < NBLKA; ++g) g_off[g * NCELL + c] += base;
}

// ---------------- kC: scatter into sorted packed SoA ----------------
__global__ void kC_scatter(const float2* __restrict__ pos,
                           const float2* __restrict__ vel)
{
    const int e    = blockIdx.x * 256 + threadIdx.x;
    const int cell = g_cellid[e];
    const int dst  = g_off[(e >> 8) * NCELL + cell] + g_lrank[e];
    const float2 p = pos[e];
    const float2 v = vel[e];
    float* P = (float*)g_pos4;
    float* V = (float*)g_vel4;
    const int b = (dst >> 1) * 4 + (dst & 1);
    P[b] = p.x;  P[b + 2] = p.y;
    V[b] = v.x;  V[b + 2] = v.y;
    g_orig[dst] = e;
    ((unsigned char*)g_scellv)[dst] = (unsigned char)cell;
}

// ---------------- k1: cull + compact + unrolled pair math + epilogue ----------------
#define PAIR_BODY(PJ, VJ)                                                     \
    {                                                                         \
        const u64 dx2 = f2add((PJ).x, nxi2);                                  \
        const u64 rxp = f2add(f2add(dx2, C2), nC2);                           \
        const u64 dwx = f2fma(rxp, nOne2, dx2);                               \
        const u64 dy2 = f2add((PJ).y, nyi2);                                  \
        const u64 ryp = f2add(f2add(dy2, C2), nC2);                           \
        const u64 dwy = f2fma(ryp, nOne2, dy2);                               \
        const u64 d2  = f2fma(dwy, dwy, f2mul(dwx, dwx));                     \
        const u64 mp  = f2mask(f2fma(d2, nOne2, perc2c), half2);              \
        const u64 ms  = f2mask(f2fma(d2, nOne2, sep2c),  half2);              \
        Px2 = f2fma(dwx, mp, Px2);                                            \
        Py2 = f2fma(dwy, mp, Py2);                                            \
        Vx2 = f2fma((VJ).x, mp, Vx2);                                         \
        Vy2 = f2fma((VJ).y, mp, Vy2);                                         \
        Cn2 = f2add(Cn2, mp);                                                 \
        Sx2 = f2fma(dwx, ms, Sx2);                                            \
        Sy2 = f2fma(dwy, ms, Sy2);                                            \
    }

__global__ __launch_bounds__(TPB1)
void k1_main(const float2* __restrict__ vel,
             const float2* __restrict__ noise,
             const float*  __restrict__ w_sep,
             const float*  __restrict__ w_ali,
             const float*  __restrict__ w_coh,
             const float*  __restrict__ w_ns,
             float2*       __restrict__ out)
{
    __shared__ unsigned s_mask[8];         // 256-bit live-cell mask
    __shared__ int      s_scan[NWARP];
    __shared__ int      s_total;
    __shared__ u16      s_pairs[NB / 2];
    __shared__ float    red[NWARP][32][8];

    const int tid  = threadIdx.x;
    const int lane = tid & 31;
    const int w    = tid >> 5;
    const int g    = blockIdx.x;           // i-tile
    const int i    = g * 32 + lane;        // every warp holds the same 32 i's

    const float* P = (const float*)g_pos4;
    const float pix = getX(P, i);
    const float piy = getY(P, i);

    // --- tile bbox (each warp computes an identical copy via shuffles) ---
    const float x0 = __shfl_sync(FULLM, pix, 0);
    const float y0 = __shfl_sync(FULLM, piy, 0);
    const float rx = wrap1(pix - x0);
    const float ry = wrap1(piy - y0);
    float mnx = rx, mxx = rx, mny = ry, mxy = ry;
    #pragma unroll
    for (int o = 16; o; o >>= 1) {
        mnx = fminf(mnx, __shfl_xor_sync(FULLM, mnx, o));
        mxx = fmaxf(mxx, __shfl_xor_sync(FULLM, mxx, o));
        mny = fminf(mny, __shfl_xor_sync(FULLM, mny, o));
        mxy = fmaxf(mxy, __shfl_xor_sync(FULLM, mxy, o));
    }
    const float bcx = x0 + 0.5f * (mnx + mxx);
    const float bcy = y0 + 0.5f * (mny + mxy);
    const float bhx = 0.5f * (mxx - mnx);
    const float bhy = 0.5f * (mxy - mny);

    // --- cull: threads 0..255 test static rect of cell tid ---
    if (tid < 256) {
        const int cy = tid >> 4;
        const int lx = tid & 15;
        const int cx = (cy & 1) ? (15 - lx) : lx;
        const float ccx = (cx + 0.5f) * (1.0f / 16.0f);
        const float ccy = (cy + 0.5f) * (1.0f / 16.0f);
        const float gx = fmaxf(0.0f, fabsf(wrap1(bcx - ccx)) - bhx - (1.0f / 32.0f) - 1e-5f);
        const float gy = fmaxf(0.0f, fabsf(wrap1(bcy - ccy)) - bhy - (1.0f / 32.0f) - 1e-5f);
        const bool live = (gx * gx + gy * gy) <= PERC2F;
        const unsigned m = __ballot_sync(FULLM, live);
        if (lane == 0) s_mask[w] = m;
    }
    __syncthreads();

    // --- pair-level liveness: thread t owns pairs [8t, 8t+8) = boids [16t, 16t+16) ---
    unsigned pl = 0;
    {
        const uint4 cv = g_scellv[tid];
        const unsigned cw[4] = {cv.x, cv.y, cv.z, cv.w};
        #pragma unroll
        for (int q = 0; q < 4; ++q) {
            const unsigned word = cw[q];
            #pragma unroll
            for (int h = 0; h < 2; ++h) {
                const unsigned ca = (word >> (h * 16)) & 0xffu;
                const unsigned cb = (word >> (h * 16 + 8)) & 0xffu;
                const unsigned lv = ((s_mask[ca >> 5] >> (ca & 31)) |
                                     (s_mask[cb >> 5] >> (cb & 31))) & 1u;
                pl |= lv << (q * 2 + h);
            }
        }
    }
    const int cntp = __popc(pl);
    int s = cntp;
    #pragma unroll
    for (int o = 1; o < 32; o <<= 1) {
        const int t = __shfl_up_sync(FULLM, s, o);
        if (lane >= o) s += t;
    }
    if (lane == 31) s_scan[w] = s;
    __syncthreads();
    if (tid == 0) {
        int acc = 0;
        #pragma unroll
        for (int k = 0; k < NWARP; ++k) { const int v = s_scan[k]; s_scan[k] = acc; acc += v; }
        s_total = acc;
    }
    __syncthreads();
    {
        int ofs = s_scan[w] + s - cntp;
        unsigned m2 = pl;
        while (m2) {
            const int b = __ffs(m2) - 1;
            m2 &= m2 - 1;
            s_pairs[ofs++] = (u16)(tid * 8 + b);
        }
    }
    __syncthreads();
    const int total = s_total;

    // --- main pair loop: warp w takes a contiguous segment, unroll 4 ---
    const u64 nxi2   = pack2(-pix, -pix);
    const u64 nyi2   = pack2(-piy, -piy);
    const u64 C2     = pack2( MAGIC,  MAGIC);
    const u64 nC2    = pack2(-MAGIC, -MAGIC);
    const u64 nOne2  = pack2(-1.0f, -1.0f);
    const u64 half2  = pack2(0.5f, 0.5f);
    const u64 sep2c  = pack2(SEP2F, SEP2F);
    const u64 perc2c = pack2(PERC2F, PERC2F);

    u64 Sx2 = 0, Sy2 = 0, Px2 = 0, Py2 = 0, Vx2 = 0, Vy2 = 0, Cn2 = 0;

    const ulonglong2* __restrict__ PP = (const ulonglong2*)g_pos4;
    const ulonglong2* __restrict__ VV = (const ulonglong2*)g_vel4;

    int k   = (total * w) >> 4;            // NWARP = 16
    const int kend = (total * (w + 1)) >> 4;

    for (; k + 3 < kend; k += 4) {
        const int i0 = s_pairs[k + 0];
        const int i1 = s_pairs[k + 1];
        const int i2 = s_pairs[k + 2];
        const int i3 = s_pairs[k + 3];
        const ulonglong2 pj0 = PP[i0];
        const ulonglong2 pj1 = PP[i1];
        const ulonglong2 pj2 = PP[i2];
        const ulonglong2 pj3 = PP[i3];
        const ulonglong2 vj0 = VV[i0];
        const ulonglong2 vj1 = VV[i1];
        const ulonglong2 vj2 = VV[i2];
        const ulonglong2 vj3 = VV[i3];
        PAIR_BODY(pj0, vj0)
        PAIR_BODY(pj1, vj1)
        PAIR_BODY(pj2, vj2)
        PAIR_BODY(pj3, vj3)
    }
    for (; k < kend; ++k) {
        const int i0 = s_pairs[k];
        const ulonglong2 pj0 = PP[i0];
        const ulonglong2 vj0 = VV[i0];
        PAIR_BODY(pj0, vj0)
    }

    // --- smem reduce (deterministic) + epilogue ---
    float a, b;
    unpack2(Sx2, a, b);  red[w][lane][0] = a + b;
    unpack2(Sy2, a, b);  red[w][lane][1] = a + b;
    unpack2(Px2, a, b);  red[w][lane][2] = a + b;
    unpack2(Py2, a, b);  red[w][lane][3] = a + b;
    unpack2(Vx2, a, b);  red[w][lane][4] = a + b;
    unpack2(Vy2, a, b);  red[w][lane][5] = a + b;
    unpack2(Cn2, a, b);  red[w][lane][6] = a + b;
    __syncthreads();

    if (tid < 32) {
        float s7[7];
        #pragma unroll
        for (int comp = 0; comp < 7; ++comp) {
            float acc = 0.0f;
            #pragma unroll
            for (int sg = 0; sg < NWARP; ++sg) acc += red[sg][tid][comp];
            s7[comp] = acc;
        }

        const float Sx = s7[0], Sy = s7[1], Px = s7[2], Py = s7[3];
        const float Vx = s7[4], Vy = s7[5];
        const float C  = s7[6] - 1.0f;       // remove self

        const int orig = g_orig[g * 32 + tid];
        const float2 vi = vel[orig];
        const float2 nz = noise[orig];

        float nrm = sqrtf(Sx * Sx + Sy * Sy);
        float inv = 1.0f / fmaxf(nrm, EPSF);
        const float sepx = -Sx * inv;
        const float sepy = -Sy * inv;

        const float invC = 1.0f / C;

        const float avx = (Vx - vi.x) * invC - vi.x;
        const float avy = (Vy - vi.y) * invC - vi.y;
        nrm = sqrtf(avx * avx + avy * avy);
        inv = 1.0f / fmaxf(nrm, EPSF);
        const float alix = avx * inv;
        const float aliy = avy * inv;

        const float cx2 = Px * invC;
        const float cy2 = Py * invC;
        nrm = sqrtf(cx2 * cx2 + cy2 * cy2);
        inv = 1.0f / fmaxf(nrm, EPSF);
        const float cohx = cx2 * inv;
        const float cohy = cy2 * inv;

        const float ws = *w_sep;
        const float wa = *w_ali;
        const float wc = *w_coh;
        const float wn = *w_ns;

        float ax = ws * sepx + wa * alix + wc * cohx + wn * nz.x;
        float ay = ws * sepy + wa * aliy + wc * cohy + wn * nz.y;

        nrm = sqrtf(ax * ax + ay * ay);
        if (nrm > 1.0f) {
            const float sc = 1.0f / fmaxf(nrm, EPSF);
            ax *= sc;
            ay *= sc;
        }

        out[orig] = make_float2(ax, ay);
    }
}

extern "C" void kernel_launch(void* const* d_in, const int* in_sizes, int n_in,
                              void* d_out, int out_size)
{
    const float2* pos   = (const float2*)d_in[0];
    const float2* vel   = (const float2*)d_in[1];
    const float2* noise = (const float2*)d_in[2];
    const float*  wsep  = (const float*)d_in[3];
    const float*  wali  = (const float*)d_in[4];
    const float*  wcoh  = (const float*)d_in[5];
    const float*  wns   = (const float*)d_in[6];
    float2* out = (float2*)d_out;

    kA_cells  <<<NBLKA, 256>>>(pos);
    kB_prefix <<<1, 256>>>();
    kC_scatter<<<NBLKA, 256>>>(pos, vel);
    k1_main   <<<NTILE, TPB1>>>(vel, noise, wsep, wali, wcoh, wns, out);
}